// round 9
// baseline (speedup 1.0000x reference)
#include <cuda_runtime.h>
#include <cuda.h>
#include <cstdint>

#define En 4096
#define Bn 8
#define HEADS 32
#define Dh 128
#define CK 128               // k-floats per chunk (TMA box dim0)
#define RB 16                // W rows per block (TMA box dim1)
#define SN 4                 // pipeline stages
#define KS 4                 // k-splits per output row
#define KCH (En / (CK * KS)) // 8 chunks per block
#define STAGE_BYTES ((RB + Bn) * CK * 4)  // 12288

typedef unsigned long long u64;

__device__ __align__(16) float g_qkv[3 * Bn * En];
__device__ __align__(16) float g_o[Bn * En];

struct Smem {
    float w[SN][RB][CK];   // 32KB
    float x[SN][Bn][CK];   // 16KB
    unsigned long long mbar[SN];
};

__device__ __forceinline__ void fma2(u64 &d, u64 a, u64 b) {
    asm("fma.rn.f32x2 %0, %1, %2, %0;" : "+l"(d) : "l"(a), "l"(b));
}
__device__ __forceinline__ float2 unpack2(u64 v) {
    float2 r; asm("mov.b64 {%0,%1}, %2;" : "=f"(r.x), "=f"(r.y) : "l"(v)); return r;
}
__device__ __forceinline__ void mbar_init(uint32_t m, uint32_t cnt) {
    asm volatile("mbarrier.init.shared.b64 [%0], %1;" :: "r"(m), "r"(cnt) : "memory");
}
__device__ __forceinline__ void mbar_expect_tx(uint32_t m, uint32_t bytes) {
    asm volatile("mbarrier.arrive.expect_tx.shared.b64 _, [%0], %1;" :: "r"(m), "r"(bytes) : "memory");
}
__device__ __forceinline__ void mbar_wait(uint32_t m, uint32_t phase) {
    asm volatile(
        "{\n\t.reg .pred P;\n\t"
        "W_%=:\n\t"
        "mbarrier.try_wait.parity.acquire.cta.shared::cta.b64 P, [%0], %1, 0x989680;\n\t"
        "@P bra.uni D_%=;\n\t"
        "bra.uni W_%=;\n\t"
        "D_%=:\n\t}"
        :: "r"(m), "r"(phase) : "memory");
}
__device__ __forceinline__ void tma2d(uint32_t dst, const CUtensorMap* tm,
                                      int cx, int cy, uint32_t mbar) {
    asm volatile(
        "cp.async.bulk.tensor.2d.shared::cta.global.tile.mbarrier::complete_tx::bytes "
        "[%0], [%1, {%2, %3}], [%4];"
        :: "r"(dst), "l"(tm), "r"(cx), "r"(cy), "r"(mbar) : "memory");
}

// epilogue: butterfly transpose-reduce of 32 per-thread partials, atomicAdd out
__device__ __forceinline__ void reduce_store(u64* acc, float* __restrict__ out,
                                             int row0, int warp, int lane) {
    float vals[32];
#pragma unroll
    for (int i = 0; i < 32; ++i) {
        float2 p = unpack2(acc[i]);
        vals[i] = p.x + p.y;
    }
    int n = 32;
#pragma unroll
    for (int m = 1; m <= 16; m <<= 1) {
        n >>= 1;
        bool up = (lane & m) != 0;
#pragma unroll
        for (int i = 0; i < n; ++i) {
            float keep = up ? vals[i + n] : vals[i];
            float send = up ? vals[i] : vals[i + n];
            keep += __shfl_xor_sync(0xffffffffu, send, m);
            vals[i] = keep;
        }
    }
    int j = ((lane & 1) << 4) | ((lane & 2) << 2) | (lane & 4) |
            ((lane >> 2) & 2) | ((lane >> 4) & 1);
    int r = j >> 3;
    int b = j & 7;
    atomicAdd(&out[(size_t)b * En + row0 + warp * 4 + r], vals[0]);
}

// Block (128 thr): 16 rows x 8 batches over k-range [k0, k0+1024).
// W tile and x tile streamed by TMA (2 ops/stage), 4-stage mbarrier ring.
__device__ __forceinline__ void gemm_tma(const CUtensorMap* __restrict__ tW,
                                         const CUtensorMap* __restrict__ tX,
                                         float* __restrict__ out,
                                         int row0, int k0) {
    extern __shared__ char smraw[];
    Smem& sm = *reinterpret_cast<Smem*>(smraw);
    const int t = threadIdx.x, warp = t >> 5, lane = t & 31;

    uint32_t swb = (uint32_t)__cvta_generic_to_shared(&sm.w[0][0][0]);
    uint32_t sxb = (uint32_t)__cvta_generic_to_shared(&sm.x[0][0][0]);
    uint32_t mb0 = (uint32_t)__cvta_generic_to_shared(&sm.mbar[0]);

    if (t == 0) {
#pragma unroll
        for (int s = 0; s < SN; ++s) mbar_init(mb0 + s * 8, 1);
    }
    __syncthreads();
    asm volatile("fence.proxy.async.shared::cta;" ::: "memory");

    auto fill = [&](int slot, int kc) {
        uint32_t m = mb0 + slot * 8;
        mbar_expect_tx(m, STAGE_BYTES);
        int cx = k0 + kc * CK;
        tma2d(swb + slot * (RB * CK * 4), tW, cx, row0, m);
        tma2d(sxb + slot * (Bn * CK * 4), tX, cx, 0, m);
    };

    if (t == 0) {
#pragma unroll
        for (int s = 0; s < SN - 1; ++s) fill(s, s);
    }

    u64 acc[32];  // [r(4)][b(8)] packed (even-k, odd-k)
#pragma unroll
    for (int i = 0; i < 32; ++i) acc[i] = 0ull;

    for (int i = 0; i < KCH; ++i) {
        int slot = i % SN;
        mbar_wait(mb0 + slot * 8, (i / SN) & 1);

        // refill the slot freed last iteration (safe: sync'd at end of iter i-1)
        int nk = i + SN - 1;
        if (t == 0 && nk < KCH) fill(nk % SN, nk);

        longlong2 wv[4];
#pragma unroll
        for (int r = 0; r < 4; ++r)
            wv[r] = *reinterpret_cast<const longlong2*>(&sm.w[slot][warp * 4 + r][lane * 4]);
#pragma unroll
        for (int b = 0; b < 8; ++b) {
            longlong2 xv = *reinterpret_cast<const longlong2*>(&sm.x[slot][b][lane * 4]);
#pragma unroll
            for (int r = 0; r < 4; ++r) {
                fma2(acc[r * 8 + b], (u64)wv[r].x, (u64)xv.x);
                fma2(acc[r * 8 + b], (u64)wv[r].y, (u64)xv.y);
            }
        }
        __syncthreads();  // all warps done with this slot before its refill
    }

    reduce_store(acc, out, row0, warp, lane);
}

// zero g_qkv (24576 float4 over 8192 threads)
__global__ void __launch_bounds__(256)
init_kernel() {
    int i = blockIdx.x * 256 + threadIdx.x;
    float4 z = make_float4(0.f, 0.f, 0.f, 0.f);
    float4* q4 = reinterpret_cast<float4*>(g_qkv);
#pragma unroll
    for (int p = 0; p < 3; ++p) q4[p * 8192 + i] = z;
}

// grid (1024, 3): blockIdx.x = rowblock*4 + ksplit; blockIdx.y = projection
__global__ void __launch_bounds__(128, 4)
qkv_kernel(const __grid_constant__ CUtensorMap tWq,
           const __grid_constant__ CUtensorMap tWk,
           const __grid_constant__ CUtensorMap tWv,
           const __grid_constant__ CUtensorMap tX) {
    int rb = blockIdx.x >> 2, ks = blockIdx.x & 3;
    const CUtensorMap* tW = (blockIdx.y == 0) ? &tWq : ((blockIdx.y == 1) ? &tWk : &tWv);
    gemm_tma(tW, &tX, g_qkv + blockIdx.y * (Bn * En), rb * RB, ks * (En / KS));
}

// Attention with all-ones KV cache collapses to o[d] = c1 + c2 * v[d] per (b,h).
// Also zero-initializes d_out for oproj's atomic accumulation.
__global__ void __launch_bounds__(256)
attn_kernel(float* __restrict__ out) {
    int gtid = blockIdx.x * blockDim.x + threadIdx.x;
    reinterpret_cast<float4*>(out)[gtid] = make_float4(0.f, 0.f, 0.f, 0.f);

    int warp = gtid >> 5;
    int lane = gtid & 31;
    int b = warp >> 5;
    int h = warp & 31;

    const float4* q4 = reinterpret_cast<const float4*>(g_qkv + (0 * Bn + b) * En + h * Dh);
    const float4* k4 = reinterpret_cast<const float4*>(g_qkv + (1 * Bn + b) * En + h * Dh);
    const float4* v4 = reinterpret_cast<const float4*>(g_qkv + (2 * Bn + b) * En + h * Dh);

    float4 qv = q4[lane];
    float4 kv = k4[lane];
    float4 vv = v4[lane];

    float sq = qv.x + qv.y + qv.z + qv.w;
    float dp = qv.x * kv.x + qv.y * kv.y + qv.z * kv.z + qv.w * kv.w;
#pragma unroll
    for (int m = 16; m >= 1; m >>= 1) {
        sq += __shfl_xor_sync(0xffffffffu, sq, m);
        dp += __shfl_xor_sync(0xffffffffu, dp, m);
    }

    const float scale = 0.08838834764831845f;  // 1/sqrt(128)
    float s0 = sq * scale;
    float sL = dp * scale;
    float mx = fmaxf(s0, sL);
    float e0 = expf(s0 - mx);
    float eL = expf(sL - mx);
    float inv = 1.0f / (4095.0f * e0 + eL);
    float c1 = 4095.0f * e0 * inv;
    float c2 = eL * inv;

    float4* o4 = reinterpret_cast<float4*>(g_o + b * En + h * Dh);
    o4[lane] = make_float4(c1 + c2 * vv.x, c1 + c2 * vv.y,
                           c1 + c2 * vv.z, c1 + c2 * vv.w);
}

// grid 1024: blockIdx.x = rowblock*4 + ksplit
__global__ void __launch_bounds__(128, 4)
oproj_kernel(const __grid_constant__ CUtensorMap tWo,
             const __grid_constant__ CUtensorMap tO,
             float* __restrict__ out) {
    int rb = blockIdx.x >> 2, ks = blockIdx.x & 3;
    gemm_tma(&tWo, &tO, out, rb * RB, ks * (En / KS));
}

// ---------------- host ----------------
typedef CUresult (*EncodeFn)(CUtensorMap*, CUtensorMapDataType, cuuint32_t, void*,
                             const cuuint64_t*, const cuuint64_t*, const cuuint32_t*,
                             const cuuint32_t*, CUtensorMapInterleave, CUtensorMapSwizzle,
                             CUtensorMapL2promotion, CUtensorMapFloatOOBfill);

static void encode_2d(EncodeFn enc, CUtensorMap* m, const void* base,
                      uint64_t rows, uint32_t box_rows) {
    cuuint64_t dims[2]    = {(cuuint64_t)En, (cuuint64_t)rows};
    cuuint64_t strides[1] = {(cuuint64_t)En * 4};
    cuuint32_t box[2]     = {(cuuint32_t)CK, box_rows};
    cuuint32_t estr[2]    = {1, 1};
    enc(m, CU_TENSOR_MAP_DATA_TYPE_FLOAT32, 2, (void*)base,
        dims, strides, box, estr,
        CU_TENSOR_MAP_INTERLEAVE_NONE, CU_TENSOR_MAP_SWIZZLE_NONE,
        CU_TENSOR_MAP_L2_PROMOTION_L2_128B, CU_TENSOR_MAP_FLOAT_OOB_FILL_NONE);
}

extern "C" void kernel_launch(void* const* d_in, const int* in_sizes, int n_in,
                              void* d_out, int out_size) {
    const float* x  = (const float*)d_in[0];
    const float* Wq = (const float*)d_in[1];
    const float* Wk = (const float*)d_in[2];
    const float* Wv = (const float*)d_in[3];
    const float* Wo = (const float*)d_in[4];
    float* out = (float*)d_out;

    static EncodeFn enc = nullptr;
    static int attr_set = 0;
    if (!attr_set) {
        cudaDriverEntryPointQueryResult qr;
        cudaGetDriverEntryPoint("cuTensorMapEncodeTiled", (void**)&enc,
                                cudaEnableDefault, &qr);
        cudaFuncSetAttribute(qkv_kernel, cudaFuncAttributeMaxDynamicSharedMemorySize,
                             (int)sizeof(Smem));
        cudaFuncSetAttribute(oproj_kernel, cudaFuncAttributeMaxDynamicSharedMemorySize,
                             (int)sizeof(Smem));
        attr_set = 1;
    }

    void* go_addr = nullptr;
    cudaGetSymbolAddress(&go_addr, g_o);

    static CUtensorMap tWq, tWk, tWv, tWo, tX, tO;
    encode_2d(enc, &tWq, Wq, En, RB);
    encode_2d(enc, &tWk, Wk, En, RB);
    encode_2d(enc, &tWv, Wv, En, RB);
    encode_2d(enc, &tWo, Wo, En, RB);
    encode_2d(enc, &tX, x, Bn, Bn);
    encode_2d(enc, &tO, go_addr, Bn, Bn);

    init_kernel<<<32, 256>>>();
    dim3 gq(1024, 3);
    qkv_kernel<<<gq, 128, sizeof(Smem)>>>(tWq, tWk, tWv, tX);
    attn_kernel<<<32, 256>>>(out);
    oproj_kernel<<<1024, 128, sizeof(Smem)>>>(tWo, tO, out);
}